// round 12
// baseline (speedup 1.0000x reference)
#include <cuda_runtime.h>
#include <math.h>

#define BN 65536
#define NDIM 32
#define HF 25
#define HV 128
#define KV 8
#define WARPS 8
#define THREADS 256
#define SPW 8
#define NITEMS (BN/SPW)
#define LDAP 132
#define LDW3 132
#define BETA 0.99f
#define TOLR 1e-4f
#define EPSV 1e-3f
#define MAX_ITER_R 1000
#define FULLM 0xffffffffu

__device__ float g_h0[KV];
__device__ int   g_ctr;

__device__ __forceinline__ float softplusf_(float x){
  float e = __expf(-fabsf(x));
  return fmaxf(x, 0.f) + __logf(1.f + e);
}
__device__ __forceinline__ void sp_sig(float p, float& sp, float& sg){
  float e = __expf(-fabsf(p));
  float inv = 1.f / (1.f + e);
  sp = fmaxf(p, 0.f) + __logf(1.f + e);
  sg = (p >= 0.f) ? inv : (1.f - inv);
}
__device__ __forceinline__ float signf_(float v){
  return (v > 0.f) ? 1.f : ((v < 0.f) ? -1.f : 0.f);
}

struct __align__(16) Smem {
  alignas(16) float W1v[NDIM*HV];         // 16KB
  alignas(16) float W2v[HV*HV];           // 64KB
  alignas(16) float W3T[KV*LDW3];         // 4.2KB transposed W3
  alignas(16) float Aw[WARPS][16][LDAP];  // 66KB padded activation scratch
  alignas(16) float C1w[WARPS][SPW][HV];  // 32KB cached F@W1v
  alignas(16) float Xw[WARPS][SPW][NDIM]; // 8KB
  alignas(16) float Fw[WARPS][SPW][NDIM]; // 8KB
  alignas(16) float Hw[WARPS][16][KV];    // 4KB
  alignas(16) float b1v[HV];
  alignas(16) float b2v[HV];
  alignas(16) float b3v[KV], h0s[KV];
  alignas(16) float W1f[NDIM*HF];
  alignas(16) float W2f[HF*HF];
  alignas(16) float W3f[HF*NDIM];
  float b1f[HF], b2f[HF], b3f[NDIM];
};

// Per-warp L2: A[R][HV] = act(A[R][HV] @ W2 + b2). Single-buffer (read all,
// syncwarp, write). PAIRED: rows (2j,2j+1) = (primal, tangent) share the exp.
template<int R, bool PAIRED>
__device__ __forceinline__ void l2_gemm(float (* __restrict__ A)[LDAP],
                                        const float* __restrict__ W2,
                                        const float* __restrict__ b2,
                                        int lane){
  const int c0 = lane * 4;
  float acc[R][4];
  #pragma unroll
  for (int r = 0; r < R; r++){ acc[r][0]=0.f; acc[r][1]=0.f; acc[r][2]=0.f; acc[r][3]=0.f; }
  #pragma unroll 1
  for (int k = 0; k < HV; k += 4){
    float4 w0 = *(const float4*)&W2[(k+0)*HV + c0];
    float4 w1 = *(const float4*)&W2[(k+1)*HV + c0];
    float4 w2 = *(const float4*)&W2[(k+2)*HV + c0];
    float4 w3 = *(const float4*)&W2[(k+3)*HV + c0];
    #pragma unroll
    for (int r = 0; r < R; r++){
      float4 a = *(const float4*)&A[r][k];
      acc[r][0]=fmaf(a.x,w0.x,fmaf(a.y,w1.x,fmaf(a.z,w2.x,fmaf(a.w,w3.x,acc[r][0]))));
      acc[r][1]=fmaf(a.x,w0.y,fmaf(a.y,w1.y,fmaf(a.z,w2.y,fmaf(a.w,w3.y,acc[r][1]))));
      acc[r][2]=fmaf(a.x,w0.z,fmaf(a.y,w1.z,fmaf(a.z,w2.z,fmaf(a.w,w3.z,acc[r][2]))));
      acc[r][3]=fmaf(a.x,w0.w,fmaf(a.y,w1.w,fmaf(a.z,w2.w,fmaf(a.w,w3.w,acc[r][3]))));
    }
  }
  __syncwarp();
  float4 bv = *(const float4*)&b2[c0];
  float bb[4] = {bv.x, bv.y, bv.z, bv.w};
  if (PAIRED){
    #pragma unroll
    for (int j = 0; j < R/2; j++){
      float pr[4], tg[4];
      #pragma unroll
      for (int v = 0; v < 4; v++){
        float p = acc[2*j][v] + bb[v];
        float sp, sg; sp_sig(p, sp, sg);
        pr[v] = sp; tg[v] = sg * acc[2*j+1][v];
      }
      *(float4*)&A[2*j  ][c0] = make_float4(pr[0],pr[1],pr[2],pr[3]);
      *(float4*)&A[2*j+1][c0] = make_float4(tg[0],tg[1],tg[2],tg[3]);
    }
  } else {
    #pragma unroll
    for (int r = 0; r < R; r++){
      float o[4];
      #pragma unroll
      for (int v = 0; v < 4; v++) o[v] = softplusf_(acc[r][v] + bb[v]);
      *(float4*)&A[r][c0] = make_float4(o[0],o[1],o[2],o[3]);
    }
  }
  __syncwarp();
}

// Per-warp L3 over 8 rows starting at A/H (caller offsets for rows 8..15).
// lane -> (row rr = lane>>2, col pair cp=(lane&3)*2), full-k per lane,
// conflict-free by LDAP/LDW3 = 132 stride argument.
// allprim: all rows get b3; else only even rows (paired primal/tangent).
__device__ __forceinline__ void l3_lane(const float (* __restrict__ A)[LDAP],
                                        const float* __restrict__ W3T,
                                        const float* __restrict__ b3,
                                        float (* __restrict__ H)[KV],
                                        int lane, bool allprim){
  const int rr = lane >> 2;
  const int cp = (lane & 3) * 2;
  float h0 = 0.f, h1 = 0.f;
  #pragma unroll 4
  for (int i = 0; i < HV; i += 4){
    float4 a  = *(const float4*)&A[rr][i];
    float4 w0 = *(const float4*)&W3T[cp*LDW3 + i];
    float4 w1 = *(const float4*)&W3T[(cp+1)*LDW3 + i];
    h0 = fmaf(a.x,w0.x,fmaf(a.y,w0.y,fmaf(a.z,w0.z,fmaf(a.w,w0.w,h0))));
    h1 = fmaf(a.x,w1.x,fmaf(a.y,w1.y,fmaf(a.z,w1.z,fmaf(a.w,w1.w,h1))));
  }
  const bool prim = allprim || ((rr & 1) == 0);
  if (prim){ h0 += b3[cp]; h1 += b3[cp+1]; }
  H[rr][cp]   = h0;
  H[rr][cp+1] = h1;
  __syncwarp();
}

__global__ void h0_kernel(const float* __restrict__ vW1, const float* __restrict__ vb1,
                          const float* __restrict__ vW2, const float* __restrict__ vb2,
                          const float* __restrict__ vW3, const float* __restrict__ vb3){
  __shared__ float h1[HV], h2[HV];
  int t = threadIdx.x;
  if (t == 0) g_ctr = 0;
  if (t < HV) h1[t] = softplusf_(vb1[t]);
  __syncthreads();
  if (t < HV){
    float acc = vb2[t];
    for (int i = 0; i < HV; i++) acc = fmaf(h1[i], vW2[i*HV + t], acc);
    h2[t] = softplusf_(acc);
  }
  __syncthreads();
  if (t < KV){
    float acc = vb3[t];
    for (int i = 0; i < HV; i++) acc = fmaf(h2[i], vW3[i*KV + t], acc);
    g_h0[t] = acc;
  }
}

__global__ void __launch_bounds__(THREADS, 1)
dyn_kernel(const float* __restrict__ x,
           const float* __restrict__ fW1, const float* __restrict__ fb1,
           const float* __restrict__ fW2, const float* __restrict__ fb2,
           const float* __restrict__ fW3, const float* __restrict__ fb3,
           const float* __restrict__ vW1, const float* __restrict__ vb1,
           const float* __restrict__ vW2, const float* __restrict__ vb2,
           const float* __restrict__ vW3, const float* __restrict__ vb3,
           float* __restrict__ out){
  extern __shared__ char smem_raw[];
  Smem& S = *reinterpret_cast<Smem*>(smem_raw);
  const int tid  = threadIdx.x;

  // ---- one-time weight load ----
  for (int i = tid; i < NDIM*HV; i += THREADS) S.W1v[i] = vW1[i];
  for (int i = tid; i < HV*HV;  i += THREADS) S.W2v[i] = vW2[i];
  for (int i = tid; i < HV*KV;  i += THREADS){
    int k = i >> 3, c = i & 7;               // vW3 is [HV][KV]
    S.W3T[c*LDW3 + k] = vW3[i];
  }
  for (int i = tid; i < HV;     i += THREADS){ S.b1v[i] = vb1[i]; S.b2v[i] = vb2[i]; }
  if (tid < KV){ S.b3v[tid] = vb3[tid]; S.h0s[tid] = g_h0[tid]; }
  for (int i = tid; i < NDIM*HF; i += THREADS) S.W1f[i] = fW1[i];
  for (int i = tid; i < HF*HF;   i += THREADS) S.W2f[i] = fW2[i];
  for (int i = tid; i < HF*NDIM; i += THREADS) S.W3f[i] = fW3[i];
  if (tid < HF){ S.b1f[tid] = fb1[tid]; S.b2f[tid] = fb2[tid]; }
  if (tid < NDIM) S.b3f[tid] = fb3[tid];
  __syncthreads();   // only block-wide barrier

  const int w    = tid >> 5;
  const int lane = tid & 31;
  const int c0   = lane * 4;
  float (* __restrict__ Awp)[LDAP] = S.Aw[w];
  float (* __restrict__ C1p)[HV]   = S.C1w[w];
  float (* __restrict__ Hwp)[KV]   = S.Hw[w];

  float4 b1q = *(const float4*)&S.b1v[c0];
  const float bb1[4] = {b1q.x, b1q.y, b1q.z, b1q.w};

  // ================= warp-autonomous persistent loop =================
  for (;;){
    int item;
    if (lane == 0) item = atomicAdd(&g_ctr, 1);
    item = __shfl_sync(FULLM, item, 0);
    if (item >= NITEMS) break;
    const size_t sbase = (size_t)item * SPW;

    // ---- load x (8 samples, 1KB coalesced) ----
    {
      const float4* xg = (const float4*)(x + sbase*NDIM);
      float4* xs = (float4*)&S.Xw[w][0][0];
      xs[lane]      = xg[lane];
      xs[lane + 32] = xg[lane + 32];
    }
    __syncwarp();

    // ---- fhat per warp: 32 -> 25 -> 25 -> 32 ----
    float* scr = &Awp[0][0];   // 2112-float scratch (overwritten later)
    if (lane < HF){
      #pragma unroll
      for (int s = 0; s < SPW; s++){
        float acc = S.b1f[lane];
        #pragma unroll
        for (int i = 0; i < NDIM; i++) acc = fmaf(S.Xw[w][s][i], S.W1f[i*HF + lane], acc);
        scr[s*HF + lane] = softplusf_(acc);
      }
    }
    __syncwarp();
    if (lane < HF){
      #pragma unroll
      for (int s = 0; s < SPW; s++){
        float acc = S.b2f[lane];
        #pragma unroll
        for (int i = 0; i < HF; i++) acc = fmaf(scr[s*HF + i], S.W2f[i*HF + lane], acc);
        scr[1024 + s*HF + lane] = softplusf_(acc);
      }
    }
    __syncwarp();
    {
      #pragma unroll
      for (int s = 0; s < SPW; s++){
        float acc = S.b3f[lane];
        #pragma unroll
        for (int i = 0; i < HF; i++) acc = fmaf(scr[1024 + s*HF + i], S.W3f[i*NDIM + lane], acc);
        S.Fw[w][s][lane] = acc;
      }
    }
    __syncwarp();

    // cached norms (lanes 0..7: sample = lane)
    float normX = 0.f, normF = 0.f;
    if (lane < SPW){
      #pragma unroll
      for (int i = 0; i < NDIM; i += 4){
        float4 xv = *(const float4*)&S.Xw[w][lane][i];
        float4 fv = *(const float4*)&S.Fw[w][lane][i];
        normX = fmaf(xv.x,xv.x,fmaf(xv.y,xv.y,fmaf(xv.z,xv.z,fmaf(xv.w,xv.w,normX))));
        normF = fmaf(fv.x,fv.x,fmaf(fv.y,fv.y,fmaf(fv.z,fv.z,fmaf(fv.w,fv.w,normF))));
      }
    }

    // ---- initial L1: rows 0..7 = x_s, rows 8..15 = F_s (all primal);
    //      raw F-row preacts cached as C1 ----
    {
      float acc[16][4];
      #pragma unroll
      for (int r = 0; r < 16; r++){ acc[r][0]=0.f; acc[r][1]=0.f; acc[r][2]=0.f; acc[r][3]=0.f; }
      #pragma unroll 1
      for (int k = 0; k < NDIM; k += 4){
        float4 w0 = *(const float4*)&S.W1v[(k+0)*HV + c0];
        float4 w1 = *(const float4*)&S.W1v[(k+1)*HV + c0];
        float4 w2 = *(const float4*)&S.W1v[(k+2)*HV + c0];
        float4 w3 = *(const float4*)&S.W1v[(k+3)*HV + c0];
        #pragma unroll
        for (int r = 0; r < 16; r++){
          const float* src = (r < 8) ? &S.Xw[w][r][0] : &S.Fw[w][r-8][0];
          float4 a = *(const float4*)&src[k];
          acc[r][0]=fmaf(a.x,w0.x,fmaf(a.y,w1.x,fmaf(a.z,w2.x,fmaf(a.w,w3.x,acc[r][0]))));
          acc[r][1]=fmaf(a.x,w0.y,fmaf(a.y,w1.y,fmaf(a.z,w2.y,fmaf(a.w,w3.y,acc[r][1]))));
          acc[r][2]=fmaf(a.x,w0.z,fmaf(a.y,w1.z,fmaf(a.z,w2.z,fmaf(a.w,w3.z,acc[r][2]))));
          acc[r][3]=fmaf(a.x,w0.w,fmaf(a.y,w1.w,fmaf(a.z,w2.w,fmaf(a.w,w3.w,acc[r][3]))));
        }
      }
      __syncwarp();   // fhat scratch reads done before Aw overwrite
      #pragma unroll
      for (int r = 8; r < 16; r++)
        *(float4*)&C1p[r-8][c0] = make_float4(acc[r][0],acc[r][1],acc[r][2],acc[r][3]);
      #pragma unroll
      for (int r = 0; r < 16; r++){
        float o[4];
        #pragma unroll
        for (int v = 0; v < 4; v++) o[v] = softplusf_(acc[r][v] + bb1[v]);
        *(float4*)&Awp[r][c0] = make_float4(o[0],o[1],o[2],o[3]);
      }
      __syncwarp();
    }
    l2_gemm<16,false>(Awp, S.W2v, S.b2v, lane);
    l3_lane(Awp,     S.W3T, S.b3v, Hwp,     lane, true);
    l3_lane(Awp + 8, S.W3T, S.b3v, Hwp + 8, lane, true);

    // ---- per-sample state (lanes 0..7) ----
    float tg = 0.f, e1l = 0.f, e2l = 1.f, s1l = 0.f, s2l = 0.f, gml = 1.f;
    int mloc = 0, violloc = 0;
    if (lane < SPW){
      float vx = EPSV * normX, vf = EPSV * normF;
      #pragma unroll
      for (int k = 0; k < KV; k++){
        float dx = Hwp[lane][k]     - S.h0s[k];
        float df = Hwp[8 + lane][k] - S.h0s[k];
        vx = fmaf(dx, dx, vx);
        vf = fmaf(df, df, vf);
      }
      tg = BETA * vx;
      float r0v = vf - tg;
      mloc = (r0v > 0.f) ? 1 : 0;
      violloc = mloc;
      s1l = signf_(-tg);
      s2l = signf_(r0v);
    }
    unsigned act = __ballot_sync(FULLM, mloc);

    // ---- Newton + bisection (per-warp, compacted to active slots) ----
    for (int it = 0; it < MAX_ITER_R && act; ++it){
      const unsigned amask = act & 0xFFu;
      const int n = __popc((int)amask);
      #pragma unroll
      for (int j = 0; j < SPW; j++){
        if ((amask >> j) & 1u){   // uniform branch (amask is warp-uniform)
          int t = __popc((int)(amask & ((1u << j) - 1u)));
          float g = __shfl_sync(FULLM, gml, j);
          float4 c = *(const float4*)&C1p[j][c0];
          float cv[4] = {c.x, c.y, c.z, c.w};
          float pr[4], tv[4];
          #pragma unroll
          for (int v = 0; v < 4; v++){
            float p = fmaf(g, cv[v], bb1[v]);
            float sp, sg; sp_sig(p, sp, sg);
            pr[v] = sp; tv[v] = sg * cv[v];
          }
          *(float4*)&Awp[2*t  ][c0] = make_float4(pr[0],pr[1],pr[2],pr[3]);
          *(float4*)&Awp[2*t+1][c0] = make_float4(tv[0],tv[1],tv[2],tv[3]);
        }
      }
      __syncwarp();
      if      (n <= 2) l2_gemm<4,true >(Awp, S.W2v, S.b2v, lane);
      else if (n <= 4) l2_gemm<8,true >(Awp, S.W2v, S.b2v, lane);
      else             l2_gemm<16,true>(Awp, S.W2v, S.b2v, lane);
      l3_lane(Awp, S.W3T, S.b3v, Hwp, lane, false);
      if (n > 4) l3_lane(Awp + 8, S.W3T, S.b3v, Hwp + 8, lane, false);

      int bis = 0;
      if (lane < SPW && mloc){
        int t = __popc((int)(amask & ((1u << lane) - 1u)));
        float g = gml;
        float vg  = EPSV * g * g * normF;
        float dvg = 2.f * EPSV * g * normF;
        #pragma unroll
        for (int k = 0; k < KV; k++){
          float d = Hwp[2*t][k] - S.h0s[k];
          vg  = fmaf(d, d, vg);
          dvg = fmaf(2.f*d, Hwp[2*t+1][k], dvg);
        }
        float resid = vg - tg;
        if (it > 0 && fabsf(resid) <= TOLR){
          mloc = 0;
        } else {
          float gn = gml - resid / dvg;
          if (!(gn >= e1l && gn <= e2l)){   // out-of-bracket OR NaN
            gml = 0.5f * (e1l + e2l);
            bis = 1;
          } else {
            gml = gn;
          }
        }
      }
      const unsigned bmask = __ballot_sync(FULLM, bis) & 0xFFu;
      if (bmask){
        const int nb = __popc((int)bmask);
        // primal-only eval at bisection midpoints, compacted to rows 0..nb-1
        #pragma unroll
        for (int j = 0; j < SPW; j++){
          if ((bmask >> j) & 1u){
            int t = __popc((int)(bmask & ((1u << j) - 1u)));
            float g = __shfl_sync(FULLM, gml, j);
            float4 c = *(const float4*)&C1p[j][c0];
            float o[4] = {
              softplusf_(fmaf(g, c.x, bb1[0])),
              softplusf_(fmaf(g, c.y, bb1[1])),
              softplusf_(fmaf(g, c.z, bb1[2])),
              softplusf_(fmaf(g, c.w, bb1[3]))};
            *(float4*)&Awp[t][c0] = make_float4(o[0],o[1],o[2],o[3]);
          }
        }
        __syncwarp();
        if (nb <= 4) l2_gemm<4,false>(Awp, S.W2v, S.b2v, lane);
        else         l2_gemm<8,false>(Awp, S.W2v, S.b2v, lane);
        l3_lane(Awp, S.W3T, S.b3v, Hwp, lane, true);
        if (lane < SPW && bis){
          int t = __popc((int)(bmask & ((1u << lane) - 1u)));
          float g = gml;
          float vg = EPSV * g * g * normF;
          #pragma unroll
          for (int k = 0; k < KV; k++){
            float d = Hwp[t][k] - S.h0s[k];
            vg = fmaf(d, d, vg);
          }
          float sa = signf_(vg - tg);
          if (sa * s1l < 0.f){ e2l = gml; s2l = sa; }
          if (sa * s2l < 0.f){ e1l = gml; s1l = sa; }
        }
      }
      act = __ballot_sync(FULLM, mloc);
    }

    // ---- output (8 samples, coalesced) ----
    #pragma unroll
    for (int j = 0; j < SPW; j++){
      float g  = __shfl_sync(FULLM, gml, j);
      int   vi = __shfl_sync(FULLM, violloc, j);
      float f  = S.Fw[w][j][lane];
      out[(sbase + j)*NDIM + lane] = vi ? f * g : f;
    }
  }
}

extern "C" void kernel_launch(void* const* d_in, const int* in_sizes, int n_in,
                              void* d_out, int out_size){
  const float* x   = (const float*)d_in[0];
  const float* fW1 = (const float*)d_in[1];
  const float* fb1 = (const float*)d_in[2];
  const float* fW2 = (const float*)d_in[3];
  const float* fb2 = (const float*)d_in[4];
  const float* fW3 = (const float*)d_in[5];
  const float* fb3 = (const float*)d_in[6];
  const float* vW1 = (const float*)d_in[7];
  const float* vb1 = (const float*)d_in[8];
  const float* vW2 = (const float*)d_in[9];
  const float* vb2 = (const float*)d_in[10];
  const float* vW3 = (const float*)d_in[11];
  const float* vb3 = (const float*)d_in[12];
  float* out = (float*)d_out;

  int dev = 0;
  cudaGetDevice(&dev);
  int sms = 148;
  cudaDeviceGetAttribute(&sms, cudaDevAttrMultiProcessorCount, dev);

  cudaFuncSetAttribute(dyn_kernel, cudaFuncAttributeMaxDynamicSharedMemorySize,
                       (int)sizeof(Smem));
  h0_kernel<<<1, 128>>>(vW1, vb1, vW2, vb2, vW3, vb3);
  dyn_kernel<<<sms, THREADS, sizeof(Smem)>>>(
      x, fW1, fb1, fW2, fb2, fW3, fb3,
      vW1, vb1, vW2, vb2, vW3, vb3, out);
}

// round 13
// speedup vs baseline: 1.2450x; 1.2450x over previous
#include <cuda_runtime.h>
#include <math.h>

#define BN 65536
#define NDIM 32
#define HF 25
#define HV 128
#define KV 8
#define WARPS 12
#define THREADS 384
#define SPW 4
#define NITEMS (BN/SPW)
#define LDAP 132
#define LDW3 132
#define BETA 0.99f
#define TOLR 1e-4f
#define EPSV 1e-3f
#define MAX_ITER_R 1000
#define FULLM 0xffffffffu

__device__ float g_h0[KV];
__device__ int   g_ctr;

// packed fp32x2 FMA: d = a*b + d (elementwise on 2 packed floats)
#define FMA2(d,a,b) asm("fma.rn.f32x2 %0, %1, %2, %0;" : "+l"(d) : "l"(a), "l"(b))

__device__ __forceinline__ float pairsum(unsigned long long v){
  float lo, hi;
  asm("mov.b64 {%0,%1}, %2;" : "=f"(lo), "=f"(hi) : "l"(v));
  return lo + hi;
}

__device__ __forceinline__ float softplusf_(float x){
  float e = __expf(-fabsf(x));
  return fmaxf(x, 0.f) + __logf(1.f + e);
}
__device__ __forceinline__ void sp_sig(float p, float& sp, float& sg){
  float e = __expf(-fabsf(p));
  float inv = 1.f / (1.f + e);
  sp = fmaxf(p, 0.f) + __logf(1.f + e);
  sg = (p >= 0.f) ? inv : (1.f - inv);
}
__device__ __forceinline__ float signf_(float v){
  return (v > 0.f) ? 1.f : ((v < 0.f) ? -1.f : 0.f);
}

struct __align__(16) Smem {
  alignas(16) float W1v[NDIM*HV];         // 16KB
  alignas(16) float W2p[HV*HV];           // 64KB, interleaved [kp][c][2]
  alignas(16) float W3T[KV*LDW3];         // 4.2KB transposed W3
  alignas(16) float Aw[WARPS][8][LDAP];   // padded activation scratch
  alignas(16) float C1w[WARPS][SPW][HV];  // cached F@W1v
  alignas(16) float Xw[WARPS][SPW][NDIM];
  alignas(16) float Fw[WARPS][SPW][NDIM];
  alignas(16) float Hw[WARPS][8][KV];
  alignas(16) float b1v[HV];
  alignas(16) float b2v[HV];
  alignas(16) float b3v[KV], h0s[KV];
  alignas(16) float W1f[NDIM*HF];
  alignas(16) float W2f[HF*HF];
  alignas(16) float W3f[HF*NDIM];
  float b1f[HF], b2f[HF], b3f[NDIM];
};

// Per-warp L2 via packed f32x2: A[R][HV] = act(A @ W2 + b2).
// k-packed accumulators (even/odd partials). Lane columns strided: c = lane+32s.
// W2p layout: W2p[kp*256 + c*2 + s] = W2[(2kp+s)*HV + c] -> W pair = one LDS.64.
// A pair = half of the existing LDS.128. Single-buffer: read all, syncwarp, write.
// PAIRED: rows (2j,2j+1) = (primal, tangent) share the exp.
template<int R, bool PAIRED>
__device__ __forceinline__ void l2_gemm(float (* __restrict__ A)[LDAP],
                                        const float* __restrict__ W2p,
                                        const float* __restrict__ b2,
                                        int lane){
  unsigned long long acc[R][4];
  #pragma unroll
  for (int r = 0; r < R; r++){ acc[r][0]=0ull; acc[r][1]=0ull; acc[r][2]=0ull; acc[r][3]=0ull; }
  #pragma unroll 1
  for (int kp2 = 0; kp2 < 64; kp2 += 2){
    unsigned long long wA[4], wB[4];
    #pragma unroll
    for (int s = 0; s < 4; s++){
      wA[s] = *(const unsigned long long*)&W2p[kp2*256 + (lane + 32*s)*2];
      wB[s] = *(const unsigned long long*)&W2p[(kp2+1)*256 + (lane + 32*s)*2];
    }
    #pragma unroll
    for (int r = 0; r < R; r++){
      ulonglong2 av = *(const ulonglong2*)&A[r][kp2*2];
      FMA2(acc[r][0], av.x, wA[0]); FMA2(acc[r][1], av.x, wA[1]);
      FMA2(acc[r][2], av.x, wA[2]); FMA2(acc[r][3], av.x, wA[3]);
      FMA2(acc[r][0], av.y, wB[0]); FMA2(acc[r][1], av.y, wB[1]);
      FMA2(acc[r][2], av.y, wB[2]); FMA2(acc[r][3], av.y, wB[3]);
    }
  }
  __syncwarp();
  float bb[4];
  #pragma unroll
  for (int s = 0; s < 4; s++) bb[s] = b2[lane + 32*s];
  if (PAIRED){
    #pragma unroll
    for (int j = 0; j < R/2; j++){
      #pragma unroll
      for (int s = 0; s < 4; s++){
        float p = pairsum(acc[2*j][s]) + bb[s];
        float t = pairsum(acc[2*j+1][s]);
        float sp, sg; sp_sig(p, sp, sg);
        A[2*j  ][lane + 32*s] = sp;
        A[2*j+1][lane + 32*s] = sg * t;
      }
    }
  } else {
    #pragma unroll
    for (int r = 0; r < R; r++){
      #pragma unroll
      for (int s = 0; s < 4; s++)
        A[r][lane + 32*s] = softplusf_(pairsum(acc[r][s]) + bb[s]);
    }
  }
  __syncwarp();
}

// Per-warp L3, packed f32x2. lane -> (row rr=lane>>2, col pair cp=(lane&3)*2).
// W3T rows are k-contiguous so W pairs come free from the float4 view.
// Conflict-free by the LDAP/LDW3=132 stride argument.
__device__ __forceinline__ void l3_lane(const float (* __restrict__ A)[LDAP],
                                        const float* __restrict__ W3T,
                                        const float* __restrict__ b3,
                                        float (* __restrict__ H)[KV],
                                        int lane, bool allprim){
  const int rr = lane >> 2;
  const int cp = (lane & 3) * 2;
  unsigned long long h0 = 0ull, h1 = 0ull;
  #pragma unroll 4
  for (int i = 0; i < HV; i += 4){
    ulonglong2 av = *(const ulonglong2*)&A[rr][i];
    ulonglong2 w0 = *(const ulonglong2*)&W3T[cp*LDW3 + i];
    ulonglong2 w1 = *(const ulonglong2*)&W3T[(cp+1)*LDW3 + i];
    FMA2(h0, av.x, w0.x); FMA2(h0, av.y, w0.y);
    FMA2(h1, av.x, w1.x); FMA2(h1, av.y, w1.y);
  }
  float h0f = pairsum(h0), h1f = pairsum(h1);
  const bool prim = allprim || ((rr & 1) == 0);
  if (prim){ h0f += b3[cp]; h1f += b3[cp+1]; }
  H[rr][cp]   = h0f;
  H[rr][cp+1] = h1f;
  __syncwarp();
}

__global__ void h0_kernel(const float* __restrict__ vW1, const float* __restrict__ vb1,
                          const float* __restrict__ vW2, const float* __restrict__ vb2,
                          const float* __restrict__ vW3, const float* __restrict__ vb3){
  __shared__ float h1[HV], h2[HV];
  int t = threadIdx.x;
  if (t == 0) g_ctr = 0;
  if (t < HV) h1[t] = softplusf_(vb1[t]);
  __syncthreads();
  if (t < HV){
    float acc = vb2[t];
    for (int i = 0; i < HV; i++) acc = fmaf(h1[i], vW2[i*HV + t], acc);
    h2[t] = softplusf_(acc);
  }
  __syncthreads();
  if (t < KV){
    float acc = vb3[t];
    for (int i = 0; i < HV; i++) acc = fmaf(h2[i], vW3[i*KV + t], acc);
    g_h0[t] = acc;
  }
}

__global__ void __launch_bounds__(THREADS, 1)
dyn_kernel(const float* __restrict__ x,
           const float* __restrict__ fW1, const float* __restrict__ fb1,
           const float* __restrict__ fW2, const float* __restrict__ fb2,
           const float* __restrict__ fW3, const float* __restrict__ fb3,
           const float* __restrict__ vW1, const float* __restrict__ vb1,
           const float* __restrict__ vW2, const float* __restrict__ vb2,
           const float* __restrict__ vW3, const float* __restrict__ vb3,
           float* __restrict__ out){
  extern __shared__ char smem_raw[];
  Smem& S = *reinterpret_cast<Smem*>(smem_raw);
  const int tid  = threadIdx.x;

  // ---- one-time weight load ----
  for (int i = tid; i < NDIM*HV; i += THREADS) S.W1v[i] = vW1[i];
  for (int i = tid; i < HV*HV;  i += THREADS){
    int kp = i >> 8, rem = i & 255, c = rem >> 1, s = rem & 1;
    S.W2p[i] = vW2[(2*kp + s)*HV + c];
  }
  for (int i = tid; i < HV*KV;  i += THREADS){
    int k = i >> 3, c = i & 7;               // vW3 is [HV][KV]
    S.W3T[c*LDW3 + k] = vW3[i];
  }
  for (int i = tid; i < HV;     i += THREADS){ S.b1v[i] = vb1[i]; S.b2v[i] = vb2[i]; }
  if (tid < KV){ S.b3v[tid] = vb3[tid]; S.h0s[tid] = g_h0[tid]; }
  for (int i = tid; i < NDIM*HF; i += THREADS) S.W1f[i] = fW1[i];
  for (int i = tid; i < HF*HF;   i += THREADS) S.W2f[i] = fW2[i];
  for (int i = tid; i < HF*NDIM; i += THREADS) S.W3f[i] = fW3[i];
  if (tid < HF){ S.b1f[tid] = fb1[tid]; S.b2f[tid] = fb2[tid]; }
  if (tid < NDIM) S.b3f[tid] = fb3[tid];
  __syncthreads();   // only block-wide barrier

  const int w    = tid >> 5;
  const int lane = tid & 31;
  const int c0   = lane * 4;
  float (* __restrict__ Awp)[LDAP] = S.Aw[w];
  float (* __restrict__ C1p)[HV]   = S.C1w[w];
  float (* __restrict__ Hwp)[KV]   = S.Hw[w];

  float4 b1q = *(const float4*)&S.b1v[c0];
  const float bb1[4] = {b1q.x, b1q.y, b1q.z, b1q.w};

  // ================= warp-autonomous persistent loop =================
  for (;;){
    int item;
    if (lane == 0) item = atomicAdd(&g_ctr, 1);
    item = __shfl_sync(FULLM, item, 0);
    if (item >= NITEMS) break;
    const size_t sbase = (size_t)item * SPW;

    // ---- load x (4 samples, 512B coalesced) ----
    ((float4*)&S.Xw[w][0][0])[lane] = ((const float4*)(x + sbase*NDIM))[lane];
    __syncwarp();

    // ---- fhat per warp: 32 -> 25 -> 25 -> 32 ----
    float* scr = &Awp[0][0];   // 1056-float scratch (overwritten later)
    if (lane < HF){
      #pragma unroll
      for (int s = 0; s < SPW; s++){
        float acc = S.b1f[lane];
        #pragma unroll
        for (int i = 0; i < NDIM; i++) acc = fmaf(S.Xw[w][s][i], S.W1f[i*HF + lane], acc);
        scr[s*HF + lane] = softplusf_(acc);
      }
    }
    __syncwarp();
    if (lane < HF){
      #pragma unroll
      for (int s = 0; s < SPW; s++){
        float acc = S.b2f[lane];
        #pragma unroll
        for (int i = 0; i < HF; i++) acc = fmaf(scr[s*HF + i], S.W2f[i*HF + lane], acc);
        scr[512 + s*HF + lane] = softplusf_(acc);
      }
    }
    __syncwarp();
    {
      #pragma unroll
      for (int s = 0; s < SPW; s++){
        float acc = S.b3f[lane];
        #pragma unroll
        for (int i = 0; i < HF; i++) acc = fmaf(scr[512 + s*HF + i], S.W3f[i*NDIM + lane], acc);
        S.Fw[w][s][lane] = acc;
      }
    }
    __syncwarp();

    // cached norms (lanes 0..3)
    float normX = 0.f, normF = 0.f;
    if (lane < SPW){
      #pragma unroll
      for (int i = 0; i < NDIM; i += 4){
        float4 xv = *(const float4*)&S.Xw[w][lane][i];
        float4 fv = *(const float4*)&S.Fw[w][lane][i];
        normX = fmaf(xv.x,xv.x,fmaf(xv.y,xv.y,fmaf(xv.z,xv.z,fmaf(xv.w,xv.w,normX))));
        normF = fmaf(fv.x,fv.x,fmaf(fv.y,fv.y,fmaf(fv.z,fv.z,fmaf(fv.w,fv.w,normF))));
      }
    }

    // ---- initial L1: rows 0..3 = x_s, rows 4..7 = F_s (all primal);
    //      raw F-row preacts cached as C1 (scalar path, once per item) ----
    {
      float acc[8][4];
      #pragma unroll
      for (int r = 0; r < 8; r++){ acc[r][0]=0.f; acc[r][1]=0.f; acc[r][2]=0.f; acc[r][3]=0.f; }
      #pragma unroll
      for (int k = 0; k < NDIM; k += 4){
        float4 w0 = *(const float4*)&S.W1v[(k+0)*HV + c0];
        float4 w1 = *(const float4*)&S.W1v[(k+1)*HV + c0];
        float4 w2 = *(const float4*)&S.W1v[(k+2)*HV + c0];
        float4 w3 = *(const float4*)&S.W1v[(k+3)*HV + c0];
        #pragma unroll
        for (int r = 0; r < 8; r++){
          const float* src = (r < 4) ? &S.Xw[w][r][0] : &S.Fw[w][r-4][0];
          float4 a = *(const float4*)&src[k];
          acc[r][0]=fmaf(a.x,w0.x,fmaf(a.y,w1.x,fmaf(a.z,w2.x,fmaf(a.w,w3.x,acc[r][0]))));
          acc[r][1]=fmaf(a.x,w0.y,fmaf(a.y,w1.y,fmaf(a.z,w2.y,fmaf(a.w,w3.y,acc[r][1]))));
          acc[r][2]=fmaf(a.x,w0.z,fmaf(a.y,w1.z,fmaf(a.z,w2.z,fmaf(a.w,w3.z,acc[r][2]))));
          acc[r][3]=fmaf(a.x,w0.w,fmaf(a.y,w1.w,fmaf(a.z,w2.w,fmaf(a.w,w3.w,acc[r][3]))));
        }
      }
      __syncwarp();   // fhat scratch reads done before Aw overwrite
      #pragma unroll
      for (int r = 4; r < 8; r++)
        *(float4*)&C1p[r-4][c0] = make_float4(acc[r][0],acc[r][1],acc[r][2],acc[r][3]);
      #pragma unroll
      for (int r = 0; r < 8; r++){
        float o[4];
        #pragma unroll
        for (int v = 0; v < 4; v++) o[v] = softplusf_(acc[r][v] + bb1[v]);
        *(float4*)&Awp[r][c0] = make_float4(o[0],o[1],o[2],o[3]);
      }
      __syncwarp();
    }
    l2_gemm<8,false>(Awp, S.W2p, S.b2v, lane);
    l3_lane(Awp, S.W3T, S.b3v, Hwp, lane, true);

    // ---- per-sample state (lanes 0..3) ----
    float tg = 0.f, e1l = 0.f, e2l = 1.f, s1l = 0.f, s2l = 0.f, gml = 1.f;
    int mloc = 0, violloc = 0;
    if (lane < SPW){
      float vx = EPSV * normX, vf = EPSV * normF;
      #pragma unroll
      for (int k = 0; k < KV; k++){
        float dx = Hwp[lane][k]     - S.h0s[k];
        float df = Hwp[4 + lane][k] - S.h0s[k];
        vx = fmaf(dx, dx, vx);
        vf = fmaf(df, df, vf);
      }
      tg = BETA * vx;
      float r0v = vf - tg;
      mloc = (r0v > 0.f) ? 1 : 0;
      violloc = mloc;
      s1l = signf_(-tg);
      s2l = signf_(r0v);
    }
    unsigned act = __ballot_sync(FULLM, mloc);

    // ---- Newton + bisection (per-warp, compacted to active slots) ----
    for (int it = 0; it < MAX_ITER_R && act; ++it){
      const unsigned amask = act & 0xFu;
      const int n = __popc((int)amask);
      #pragma unroll
      for (int j = 0; j < SPW; j++){
        if ((amask >> j) & 1u){   // uniform branch (amask is warp-uniform)
          int t = __popc((int)(amask & ((1u << j) - 1u)));
          float g = __shfl_sync(FULLM, gml, j);
          float4 c = *(const float4*)&C1p[j][c0];
          float cv[4] = {c.x, c.y, c.z, c.w};
          float pr[4], tv[4];
          #pragma unroll
          for (int v = 0; v < 4; v++){
            float p = fmaf(g, cv[v], bb1[v]);
            float sp, sg; sp_sig(p, sp, sg);
            pr[v] = sp; tv[v] = sg * cv[v];
          }
          *(float4*)&Awp[2*t  ][c0] = make_float4(pr[0],pr[1],pr[2],pr[3]);
          *(float4*)&Awp[2*t+1][c0] = make_float4(tv[0],tv[1],tv[2],tv[3]);
        }
      }
      __syncwarp();
      if (n <= 2) l2_gemm<4,true>(Awp, S.W2p, S.b2v, lane);
      else        l2_gemm<8,true>(Awp, S.W2p, S.b2v, lane);
      l3_lane(Awp, S.W3T, S.b3v, Hwp, lane, false);

      int bis = 0;
      if (lane < SPW && mloc){
        int t = __popc((int)(amask & ((1u << lane) - 1u)));
        float g = gml;
        float vg  = EPSV * g * g * normF;
        float dvg = 2.f * EPSV * g * normF;
        #pragma unroll
        for (int k = 0; k < KV; k++){
          float d = Hwp[2*t][k] - S.h0s[k];
          vg  = fmaf(d, d, vg);
          dvg = fmaf(2.f*d, Hwp[2*t+1][k], dvg);
        }
        float resid = vg - tg;
        if (it > 0 && fabsf(resid) <= TOLR){
          mloc = 0;
        } else {
          float gn = gml - resid / dvg;
          if (!(gn >= e1l && gn <= e2l)){   // out-of-bracket OR NaN
            gml = 0.5f * (e1l + e2l);
            bis = 1;
          } else {
            gml = gn;
          }
        }
      }
      const unsigned bmask = __ballot_sync(FULLM, bis) & 0xFu;
      if (bmask){
        // primal-only eval at bisection midpoints, compacted
        #pragma unroll
        for (int j = 0; j < SPW; j++){
          if ((bmask >> j) & 1u){
            int t = __popc((int)(bmask & ((1u << j) - 1u)));
            float g = __shfl_sync(FULLM, gml, j);
            float4 c = *(const float4*)&C1p[j][c0];
            float o[4] = {
              softplusf_(fmaf(g, c.x, bb1[0])),
              softplusf_(fmaf(g, c.y, bb1[1])),
              softplusf_(fmaf(g, c.z, bb1[2])),
              softplusf_(fmaf(g, c.w, bb1[3]))};
            *(float4*)&Awp[t][c0] = make_float4(o[0],o[1],o[2],o[3]);
          }
        }
        __syncwarp();
        l2_gemm<4,false>(Awp, S.W2p, S.b2v, lane);
        l3_lane(Awp, S.W3T, S.b3v, Hwp, lane, true);
        if (lane < SPW && bis){
          int t = __popc((int)(bmask & ((1u << lane) - 1u)));
          float g = gml;
          float vg = EPSV * g * g * normF;
          #pragma unroll
          for (int k = 0; k < KV; k++){
            float d = Hwp[t][k] - S.h0s[k];
            vg = fmaf(d, d, vg);
          }
          float sa = signf_(vg - tg);
          if (sa * s1l < 0.f){ e2l = gml; s2l = sa; }
          if (sa * s2l < 0.f){ e1l = gml; s1l = sa; }
        }
      }
      act = __ballot_sync(FULLM, mloc);
    }

    // ---- output (4 samples, coalesced) ----
    #pragma unroll
    for (int j = 0; j < SPW; j++){
      float g  = __shfl_sync(FULLM, gml, j);
      int   vi = __shfl_sync(FULLM, violloc, j);
      float f  = S.Fw[w][j][lane];
      out[(sbase + j)*NDIM + lane] = vi ? f * g : f;
    }
  }
}

extern "C" void kernel_launch(void* const* d_in, const int* in_sizes, int n_in,
                              void* d_out, int out_size){
  const float* x   = (const float*)d_in[0];
  const float* fW1 = (const float*)d_in[1];
  const float* fb1 = (const float*)d_in[2];
  const float* fW2 = (const float*)d_in[3];
  const float* fb2 = (const float*)d_in[4];
  const float* fW3 = (const float*)d_in[5];
  const float* fb3 = (const float*)d_in[6];
  const float* vW1 = (const float*)d_in[7];
  const float* vb1 = (const float*)d_in[8];
  const float* vW2 = (const float*)d_in[9];
  const float* vb2 = (const float*)d_in[10];
  const float* vW3 = (const float*)d_in[11];
  const float* vb3 = (const float*)d_in[12];
  float* out = (float*)d_out;

  int dev = 0;
  cudaGetDevice(&dev);
  int sms = 148;
  cudaDeviceGetAttribute(&sms, cudaDevAttrMultiProcessorCount, dev);

  cudaFuncSetAttribute(dyn_kernel, cudaFuncAttributeMaxDynamicSharedMemorySize,
                       (int)sizeof(Smem));
  h0_kernel<<<1, 128>>>(vW1, vb1, vW2, vb2, vW3, vb3);
  dyn_kernel<<<sms, THREADS, sizeof(Smem)>>>(
      x, fW1, fb1, fW2, fb2, fW3, fb3,
      vW1, vb1, vW2, vb2, vW3, vb3, out);
}

// round 15
// speedup vs baseline: 1.2989x; 1.0434x over previous
#include <cuda_runtime.h>
#include <math.h>

#define BN 65536
#define NDIM 32
#define HF 25
#define HV 128
#define KV 8
#define WARPS 16
#define THREADS 512
#define PAIRS 8
#define SPP 8                 // samples per pair-item
#define NITEMS (BN/SPP)
#define LDAP 132
#define LDW3 132
#define BETA 0.99f
#define TOLR 1e-4f
#define EPSV 1e-3f
#define MAX_ITER_R 1000
#define FULLM 0xffffffffu

#define BARP() asm volatile("bar.sync %0, %1;" :: "r"(barid), "r"(64) : "memory")

__device__ float g_h0[KV];
__device__ int   g_ctr;

__device__ __forceinline__ float softplusf_(float x){
  float e = __expf(-fabsf(x));
  return fmaxf(x, 0.f) + __logf(1.f + e);
}
__device__ __forceinline__ void sp_sig(float p, float& sp, float& sg){
  float e = __expf(-fabsf(p));
  float inv = 1.f / (1.f + e);
  sp = fmaxf(p, 0.f) + __logf(1.f + e);
  sg = (p >= 0.f) ? inv : (1.f - inv);
}
__device__ __forceinline__ float signf_(float v){
  return (v > 0.f) ? 1.f : ((v < 0.f) ? -1.f : 0.f);
}

struct __align__(16) Smem {
  alignas(16) float W1v[NDIM*HV];          // 16KB
  alignas(16) float W2v[HV*HV];            // 64KB row-major
  alignas(16) float W3T[KV*LDW3];          // 4.2KB transposed W3
  alignas(16) float Aw[PAIRS][16][LDAP];   // 67.6KB per-pair activation scratch
  alignas(16) float C1w[PAIRS][SPP][HV];   // 32KB cached F@W1v
  alignas(16) float Xw[PAIRS][SPP][NDIM];  // 8KB
  alignas(16) float Fw[PAIRS][SPP][NDIM];  // 8KB
  alignas(16) float Hw[PAIRS][16][KV];     // 4KB
  alignas(16) float b1v[HV];
  alignas(16) float b2v[HV];
  alignas(16) float b3v[KV], h0s[KV];
  alignas(16) float W1f[NDIM*HF];
  alignas(16) float W2f[HF*HF];
  alignas(16) float W3f[HF*NDIM];
  float b1f[HF], b2f[HF], b3f[NDIM];
  int   Ctl[PAIRS][6];   // [0]=item [1,2]=act masks [3,4]=bis masks
};

// Pair-cooperative L2: A[R][HV] = act(A[R][HV] @ W2 + b2).
// Warp hw computes columns [64hw, 64hw+64), 2 per lane: c = 64hw + 2lane.
// Mid bar separates read phase (all cols of A) from write phase (own cols).
// PAIRED: rows (2j,2j+1) = (primal, tangent) share the exp.
template<int R, bool PAIRED>
__device__ __forceinline__ void l2_pair(float (* __restrict__ A)[LDAP],
                                        const float* __restrict__ W2,
                                        const float* __restrict__ b2,
                                        int lane, int hw, int barid){
  const int c = 64*hw + 2*lane;
  float acc[R][2];
  #pragma unroll
  for (int r = 0; r < R; r++){ acc[r][0] = 0.f; acc[r][1] = 0.f; }
  #pragma unroll 2
  for (int k4 = 0; k4 < HV; k4 += 4){
    float2 w0 = *(const float2*)&W2[(k4+0)*HV + c];
    float2 w1 = *(const float2*)&W2[(k4+1)*HV + c];
    float2 w2 = *(const float2*)&W2[(k4+2)*HV + c];
    float2 w3 = *(const float2*)&W2[(k4+3)*HV + c];
    #pragma unroll
    for (int r = 0; r < R; r++){
      float4 a = *(const float4*)&A[r][k4];
      acc[r][0]=fmaf(a.x,w0.x,fmaf(a.y,w1.x,fmaf(a.z,w2.x,fmaf(a.w,w3.x,acc[r][0]))));
      acc[r][1]=fmaf(a.x,w0.y,fmaf(a.y,w1.y,fmaf(a.z,w2.y,fmaf(a.w,w3.y,acc[r][1]))));
    }
  }
  BARP();   // both warps done reading A before either overwrites it
  float2 bv = *(const float2*)&b2[c];
  if (PAIRED){
    #pragma unroll
    for (int j = 0; j < R/2; j++){
      float sp0, sg0, sp1, sg1;
      sp_sig(acc[2*j][0] + bv.x, sp0, sg0);
      sp_sig(acc[2*j][1] + bv.y, sp1, sg1);
      *(float2*)&A[2*j  ][c] = make_float2(sp0, sp1);
      *(float2*)&A[2*j+1][c] = make_float2(sg0*acc[2*j+1][0], sg1*acc[2*j+1][1]);
    }
  } else {
    #pragma unroll
    for (int r = 0; r < R; r++){
      *(float2*)&A[r][c] = make_float2(softplusf_(acc[r][0] + bv.x),
                                       softplusf_(acc[r][1] + bv.y));
    }
  }
  // caller issues the post-write barrier
}

// Per-warp L3 over 8 rows at A/H base. lane -> (row rr=lane>>2, col pair
// cp=(lane&3)*2), full-k per lane, conflict-free by LDAP/LDW3=132 strides.
__device__ __forceinline__ void l3_lane(const float (* __restrict__ A)[LDAP],
                                        const float* __restrict__ W3T,
                                        const float* __restrict__ b3,
                                        float (* __restrict__ H)[KV],
                                        int lane, bool allprim){
  const int rr = lane >> 2;
  const int cp = (lane & 3) * 2;
  float h0 = 0.f, h1 = 0.f;
  #pragma unroll 4
  for (int i = 0; i < HV; i += 4){
    float4 a  = *(const float4*)&A[rr][i];
    float4 w0 = *(const float4*)&W3T[cp*LDW3 + i];
    float4 w1 = *(const float4*)&W3T[(cp+1)*LDW3 + i];
    h0 = fmaf(a.x,w0.x,fmaf(a.y,w0.y,fmaf(a.z,w0.z,fmaf(a.w,w0.w,h0))));
    h1 = fmaf(a.x,w1.x,fmaf(a.y,w1.y,fmaf(a.z,w1.z,fmaf(a.w,w1.w,h1))));
  }
  const bool prim = allprim || ((rr & 1) == 0);
  if (prim){ h0 += b3[cp]; h1 += b3[cp+1]; }
  H[rr][cp]   = h0;
  H[rr][cp+1] = h1;
  __syncwarp();
}

__global__ void h0_kernel(const float* __restrict__ vW1, const float* __restrict__ vb1,
                          const float* __restrict__ vW2, const float* __restrict__ vb2,
                          const float* __restrict__ vW3, const float* __restrict__ vb3){
  __shared__ float h1[HV], h2[HV];
  int t = threadIdx.x;
  if (t == 0) g_ctr = 0;
  if (t < HV) h1[t] = softplusf_(vb1[t]);
  __syncthreads();
  if (t < HV){
    float acc = vb2[t];
    for (int i = 0; i < HV; i++) acc = fmaf(h1[i], vW2[i*HV + t], acc);
    h2[t] = softplusf_(acc);
  }
  __syncthreads();
  if (t < KV){
    float acc = vb3[t];
    for (int i = 0; i < HV; i++) acc = fmaf(h2[i], vW3[i*KV + t], acc);
    g_h0[t] = acc;
  }
}

__global__ void __launch_bounds__(THREADS, 1)
dyn_kernel(const float* __restrict__ x,
           const float* __restrict__ fW1, const float* __restrict__ fb1,
           const float* __restrict__ fW2, const float* __restrict__ fb2,
           const float* __restrict__ fW3, const float* __restrict__ fb3,
           const float* __restrict__ vW1, const float* __restrict__ vb1,
           const float* __restrict__ vW2, const float* __restrict__ vb2,
           const float* __restrict__ vW3, const float* __restrict__ vb3,
           float* __restrict__ out){
  extern __shared__ char smem_raw[];
  Smem& S = *reinterpret_cast<Smem*>(smem_raw);
  const int tid  = threadIdx.x;

  // ---- one-time weight load ----
  for (int i = tid; i < NDIM*HV; i += THREADS) S.W1v[i] = vW1[i];
  for (int i = tid; i < HV*HV;  i += THREADS) S.W2v[i] = vW2[i];
  for (int i = tid; i < HV*KV;  i += THREADS){
    int k = i >> 3, c = i & 7;               // vW3 is [HV][KV]
    S.W3T[c*LDW3 + k] = vW3[i];
  }
  for (int i = tid; i < HV;     i += THREADS){ S.b1v[i] = vb1[i]; S.b2v[i] = vb2[i]; }
  if (tid < KV){ S.b3v[tid] = vb3[tid]; S.h0s[tid] = g_h0[tid]; }
  for (int i = tid; i < NDIM*HF; i += THREADS) S.W1f[i] = fW1[i];
  for (int i = tid; i < HF*HF;   i += THREADS) S.W2f[i] = fW2[i];
  for (int i = tid; i < HF*NDIM; i += THREADS) S.W3f[i] = fW3[i];
  if (tid < HF){ S.b1f[tid] = fb1[tid]; S.b2f[tid] = fb2[tid]; }
  if (tid < NDIM) S.b3f[tid] = fb3[tid];
  __syncthreads();   // only block-wide barrier

  const int w     = tid >> 5;
  const int lane  = tid & 31;
  const int p     = w >> 1;       // pair id
  const int hw    = w & 1;        // warp within pair
  const int barid = 1 + p;        // named barrier per pair (ids 1..8)
  const int c0    = lane * 4;
  float (* __restrict__ Awp)[LDAP] = S.Aw[p];
  float (* __restrict__ C1p)[HV]   = S.C1w[p];
  float (* __restrict__ Hwp)[KV]   = S.Hw[p];

  float4 b1q = *(const float4*)&S.b1v[c0];
  const float bb1[4] = {b1q.x, b1q.y, b1q.z, b1q.w};

  // ================= pair-cooperative persistent loop =================
  for (;;){
    if (hw == 0 && lane == 0) S.Ctl[p][0] = atomicAdd(&g_ctr, 1);
    BARP();
    const int item = S.Ctl[p][0];
    if (item >= NITEMS) break;
    const size_t sbase = (size_t)item * SPP;

    // ---- load own 4 samples' x (coalesced halves of the 1KB item) ----
    {
      const float4* xg = (const float4*)(x + sbase*NDIM);
      float4* xs = (float4*)&S.Xw[p][0][0];
      xs[hw*32 + lane] = xg[hw*32 + lane];
    }
    __syncwarp();

    // ---- fhat for own 4 samples (scratch = own 8 rows of Awp) ----
    float* scr = &Awp[8*hw][0];   // 1056 floats, own half
    if (lane < HF){
      #pragma unroll
      for (int s = 0; s < 4; s++){
        float acc = S.b1f[lane];
        #pragma unroll
        for (int i = 0; i < NDIM; i++) acc = fmaf(S.Xw[p][4*hw+s][i], S.W1f[i*HF + lane], acc);
        scr[s*HF + lane] = softplusf_(acc);
      }
    }
    __syncwarp();
    if (lane < HF){
      #pragma unroll
      for (int s = 0; s < 4; s++){
        float acc = S.b2f[lane];
        #pragma unroll
        for (int i = 0; i < HF; i++) acc = fmaf(scr[s*HF + i], S.W2f[i*HF + lane], acc);
        scr[512 + s*HF + lane] = softplusf_(acc);
      }
    }
    __syncwarp();
    {
      #pragma unroll
      for (int s = 0; s < 4; s++){
        float acc = S.b3f[lane];
        #pragma unroll
        for (int i = 0; i < HF; i++) acc = fmaf(scr[512 + s*HF + i], S.W3f[i*NDIM + lane], acc);
        S.Fw[p][4*hw+s][lane] = acc;
      }
    }
    __syncwarp();

    // cached norms for own samples (lanes 0..3 -> sample 4hw+lane)
    float normX = 0.f, normF = 0.f;
    if (lane < 4){
      #pragma unroll
      for (int i = 0; i < NDIM; i += 4){
        float4 xv = *(const float4*)&S.Xw[p][4*hw+lane][i];
        float4 fv = *(const float4*)&S.Fw[p][4*hw+lane][i];
        normX = fmaf(xv.x,xv.x,fmaf(xv.y,xv.y,fmaf(xv.z,xv.z,fmaf(xv.w,xv.w,normX))));
        normF = fmaf(fv.x,fv.x,fmaf(fv.y,fv.y,fmaf(fv.z,fv.z,fmaf(fv.w,fv.w,normF))));
      }
    }
    BARP();   // scratch regions free before L1 writes cross into them

    // ---- initial L1 for own 8 rows: x rows at [4hw..4hw+3], F rows at
    //      [8+4hw..8+4hw+3]; F-row preacts cached as C1 ----
    {
      float acc[8][4];
      #pragma unroll
      for (int r = 0; r < 8; r++){ acc[r][0]=0.f; acc[r][1]=0.f; acc[r][2]=0.f; acc[r][3]=0.f; }
      #pragma unroll
      for (int k = 0; k < NDIM; k += 4){
        float4 w0 = *(const float4*)&S.W1v[(k+0)*HV + c0];
        float4 w1 = *(const float4*)&S.W1v[(k+1)*HV + c0];
        float4 w2 = *(const float4*)&S.W1v[(k+2)*HV + c0];
        float4 w3 = *(const float4*)&S.W1v[(k+3)*HV + c0];
        #pragma unroll
        for (int r = 0; r < 8; r++){
          const float* src = (r < 4) ? &S.Xw[p][4*hw + r][0] : &S.Fw[p][4*hw + r - 4][0];
          float4 a = *(const float4*)&src[k];
          acc[r][0]=fmaf(a.x,w0.x,fmaf(a.y,w1.x,fmaf(a.z,w2.x,fmaf(a.w,w3.x,acc[r][0]))));
          acc[r][1]=fmaf(a.x,w0.y,fmaf(a.y,w1.y,fmaf(a.z,w2.y,fmaf(a.w,w3.y,acc[r][1]))));
          acc[r][2]=fmaf(a.x,w0.z,fmaf(a.y,w1.z,fmaf(a.z,w2.z,fmaf(a.w,w3.z,acc[r][2]))));
          acc[r][3]=fmaf(a.x,w0.w,fmaf(a.y,w1.w,fmaf(a.z,w2.w,fmaf(a.w,w3.w,acc[r][3]))));
        }
      }
      #pragma unroll
      for (int r = 4; r < 8; r++)
        *(float4*)&C1p[4*hw + r - 4][c0] = make_float4(acc[r][0],acc[r][1],acc[r][2],acc[r][3]);
      #pragma unroll
      for (int r = 0; r < 8; r++){
        int row = (r < 4) ? (4*hw + r) : (8 + 4*hw + r - 4);
        float o[4];
        #pragma unroll
        for (int v = 0; v < 4; v++) o[v] = softplusf_(acc[r][v] + bb1[v]);
        *(float4*)&Awp[row][c0] = make_float4(o[0],o[1],o[2],o[3]);
      }
    }
    BARP();
    l2_pair<16,false>(Awp, S.W2v, S.b2v, lane, hw, barid);
    BARP();
    l3_lane(Awp + 8*hw, S.W3T, S.b3v, Hwp + 8*hw, lane, true);
    BARP();

    // ---- per-sample state (own lanes 0..3, global sample gj = 4hw+lane) ----
    float tg = 0.f, e1l = 0.f, e2l = 1.f, s1l = 0.f, s2l = 0.f, gml = 1.f;
    int mloc = 0, violloc = 0;
    if (lane < 4){
      int gj = 4*hw + lane;
      float vx = EPSV * normX, vf = EPSV * normF;
      #pragma unroll
      for (int k = 0; k < KV; k++){
        float dx = Hwp[gj][k]     - S.h0s[k];
        float df = Hwp[8 + gj][k] - S.h0s[k];
        vx = fmaf(dx, dx, vx);
        vf = fmaf(df, df, vf);
      }
      tg = BETA * vx;
      float r0v = vf - tg;
      mloc = (r0v > 0.f) ? 1 : 0;
      violloc = mloc;
      s1l = signf_(-tg);
      s2l = signf_(r0v);
    }
    {
      unsigned m4 = __ballot_sync(FULLM, mloc) & 0xFu;
      if (lane == 0) S.Ctl[p][1 + hw] = (int)m4;
    }
    BARP();
    unsigned amask8 = (unsigned)S.Ctl[p][1] | ((unsigned)S.Ctl[p][2] << 4);

    // ---- Newton + bisection (pair-cooperative, compacted) ----
    for (int it = 0; it < MAX_ITER_R && amask8; ++it){
      const int n = __popc((int)amask8);
      // build rows for OWN active samples at global slots
      #pragma unroll
      for (int j = 0; j < 4; j++){
        int gj = 4*hw + j;
        if ((amask8 >> gj) & 1u){   // pair-uniform per gj? no — but warp-uniform (amask8 uniform)
          int t = __popc((int)(amask8 & ((1u << gj) - 1u)));
          float g = __shfl_sync(FULLM, gml, j);
          float4 c = *(const float4*)&C1p[gj][c0];
          float cv[4] = {c.x, c.y, c.z, c.w};
          float pr[4], tv[4];
          #pragma unroll
          for (int v = 0; v < 4; v++){
            float pp = fmaf(g, cv[v], bb1[v]);
            float sp, sg; sp_sig(pp, sp, sg);
            pr[v] = sp; tv[v] = sg * cv[v];
          }
          *(float4*)&Awp[2*t  ][c0] = make_float4(pr[0],pr[1],pr[2],pr[3]);
          *(float4*)&Awp[2*t+1][c0] = make_float4(tv[0],tv[1],tv[2],tv[3]);
        }
      }
      BARP();
      if      (n <= 2) l2_pair<4 ,true>(Awp, S.W2v, S.b2v, lane, hw, barid);
      else if (n <= 4) l2_pair<8 ,true>(Awp, S.W2v, S.b2v, lane, hw, barid);
      else             l2_pair<16,true>(Awp, S.W2v, S.b2v, lane, hw, barid);
      BARP();
      if (n <= 4){
        if (hw == 0) l3_lane(Awp, S.W3T, S.b3v, Hwp, lane, false);
      } else {
        l3_lane(Awp + 8*hw, S.W3T, S.b3v, Hwp + 8*hw, lane, false);
      }
      BARP();

      int bis = 0;
      if (lane < 4 && mloc){
        int gj = 4*hw + lane;
        int t = __popc((int)(amask8 & ((1u << gj) - 1u)));
        float g = gml;
        float vg  = EPSV * g * g * normF;
        float dvg = 2.f * EPSV * g * normF;
        #pragma unroll
        for (int k = 0; k < KV; k++){
          float d = Hwp[2*t][k] - S.h0s[k];
          vg  = fmaf(d, d, vg);
          dvg = fmaf(2.f*d, Hwp[2*t+1][k], dvg);
        }
        float resid = vg - tg;
        if (it > 0 && fabsf(resid) <= TOLR){
          mloc = 0;
        } else {
          float gn = gml - resid / dvg;
          if (!(gn >= e1l && gn <= e2l)){   // out-of-bracket OR NaN
            gml = 0.5f * (e1l + e2l);
            bis = 1;
          } else {
            gml = gn;
          }
        }
      }
      {
        unsigned m4b = __ballot_sync(FULLM, bis) & 0xFu;
        if (lane == 0) S.Ctl[p][3 + hw] = (int)m4b;
      }
      BARP();
      unsigned bmask8 = (unsigned)S.Ctl[p][3] | ((unsigned)S.Ctl[p][4] << 4);
      if (bmask8){
        const int nb = __popc((int)bmask8);
        #pragma unroll
        for (int j = 0; j < 4; j++){
          int gj = 4*hw + j;
          if ((bmask8 >> gj) & 1u){
            int t = __popc((int)(bmask8 & ((1u << gj) - 1u)));
            float g = __shfl_sync(FULLM, gml, j);
            float4 c = *(const float4*)&C1p[gj][c0];
            float o[4] = {
              softplusf_(fmaf(g, c.x, bb1[0])),
              softplusf_(fmaf(g, c.y, bb1[1])),
              softplusf_(fmaf(g, c.z, bb1[2])),
              softplusf_(fmaf(g, c.w, bb1[3]))};
            *(float4*)&Awp[t][c0] = make_float4(o[0],o[1],o[2],o[3]);
          }
        }
        BARP();
        if (nb <= 4) l2_pair<4,false>(Awp, S.W2v, S.b2v, lane, hw, barid);
        else         l2_pair<8,false>(Awp, S.W2v, S.b2v, lane, hw, barid);
        BARP();
        if (hw == 0) l3_lane(Awp, S.W3T, S.b3v, Hwp, lane, true);
        BARP();
        if (lane < 4 && bis){
          int gj = 4*hw + lane;
          int t = __popc((int)(bmask8 & ((1u << gj) - 1u)));
          float g = gml;
          float vg = EPSV * g * g * normF;
          #pragma unroll
          for (int k = 0; k < KV; k++){
            float d = Hwp[t][k] - S.h0s[k];
            vg = fmaf(d, d, vg);
          }
          float sa = signf_(vg - tg);
          if (sa * s1l < 0.f){ e2l = gml; s2l = sa; }
          if (sa * s2l < 0.f){ e1l = gml; s1l = sa; }
        }
      }
      {
        unsigned m4 = __ballot_sync(FULLM, mloc) & 0xFu;
        if (lane == 0) S.Ctl[p][1 + hw] = (int)m4;
      }
      BARP();
      amask8 = (unsigned)S.Ctl[p][1] | ((unsigned)S.Ctl[p][2] << 4);
    }

    // ---- output own 4 samples (coalesced) ----
    #pragma unroll
    for (int j = 0; j < 4; j++){
      int gj = 4*hw + j;
      float g  = __shfl_sync(FULLM, gml, j);
      int   vi = __shfl_sync(FULLM, violloc, j);
      float f  = S.Fw[p][gj][lane];
      out[(sbase + gj)*NDIM + lane] = vi ? f * g : f;
    }
    __syncwarp();
  }
}

extern "C" void kernel_launch(void* const* d_in, const int* in_sizes, int n_in,
                              void* d_out, int out_size){
  const float* x   = (const float*)d_in[0];
  const float* fW1 = (const float*)d_in[1];
  const float* fb1 = (const float*)d_in[2];
  const float* fW2 = (const float*)d_in[3];
  const float* fb2 = (const float*)d_in[4];
  const float* fW3 = (const float*)d_in[5];
  const float* fb3 = (const float*)d_in[6];
  const float* vW1 = (const float*)d_in[7];
  const float* vb1 = (const float*)d_in[8];
  const float* vW2 = (const float*)d_in[9];
  const float* vb2 = (const float*)d_in[10];
  const float* vW3 = (const float*)d_in[11];
  const float* vb3 = (const float*)d_in[12];
  float* out = (float*)d_out;

  int dev = 0;
  cudaGetDevice(&dev);
  int sms = 148;
  cudaDeviceGetAttribute(&sms, cudaDevAttrMultiProcessorCount, dev);

  cudaFuncSetAttribute(dyn_kernel, cudaFuncAttributeMaxDynamicSharedMemorySize,
                       (int)sizeof(Smem));
  h0_kernel<<<1, 128>>>(vW1, vb1, vW2, vb2, vW3, vb3);
  dyn_kernel<<<sms, THREADS, sizeof(Smem)>>>(
      x, fW1, fb1, fW2, fb2, fW3, fb3,
      vW1, vb1, vW2, vb2, vW3, vb3, out);
}